// round 16
// baseline (speedup 1.0000x reference)
#include <cuda_runtime.h>
#include <cstdint>

// Complex attention, single-pass TF32 mma.m16n8k8. B=8 H=8 S=1024 D=64.
// R16: pair-permuted smem columns (logical c -> slot; pair (c,c+4) adjacent)
// so A/B fragment loads are float2 (LDS.64) with zero address ALU; fills keep
// single STS.64 per array (thread owns cols (c,c+4)). V PAD 72 (conflict-free).
// K1: attn=(q/8).k -> spill + per-(row,ktile) mag^2 min/max  [128q x 64k]
// K2: row min/max reduce
// K3: normalize(attn) @ v                                    [128q x 64d]

#define NKT 16
typedef unsigned long long u64;
typedef uint32_t u32;

__device__ float g_ar[(size_t)64 * 1024 * 1024];   // 256 MB
__device__ float g_ai[(size_t)64 * 1024 * 1024];   // 256 MB
__device__ float g_pmin[64 * 1024 * NKT];
__device__ float g_pmax[64 * 1024 * NKT];
__device__ float g_mn[64 * 1024];
__device__ float g_inv[64 * 1024];

#define PAD 72               // u32/row (64 data + 8 pad)
#define NEGF 0x80000000u
#define QW (128 * PAD)
#define KW (64 * PAD)

__device__ __forceinline__ u32 tf32c(float x) {
    u32 r; asm("cvt.rna.tf32.f32 %0, %1;" : "=r"(r) : "f"(x)); return r;
}
__device__ __forceinline__ u64 pk2(u32 lo, u32 hi) {
    return (u64)lo | ((u64)hi << 32);
}
__device__ __forceinline__ void mma_tf32(float* c, const u32* a, const u32* b) {
    asm volatile("mma.sync.aligned.m16n8k8.row.col.f32.tf32.tf32.f32 "
        "{%0,%1,%2,%3}, {%4,%5,%6,%7}, {%8,%9}, {%0,%1,%2,%3};"
        : "+f"(c[0]), "+f"(c[1]), "+f"(c[2]), "+f"(c[3])
        : "r"(a[0]), "r"(a[1]), "r"(a[2]), "r"(a[3]), "r"(b[0]), "r"(b[1]));
}
__device__ __forceinline__ u32 f2u(float x) { return __float_as_uint(x); }

// ---------------------------------------------------------------------------
// K1: QK. CTA tile 128q x 64k, 8 warps (4m x 2n), warp tile 32q x 32k.
// Permuted columns: logical (8v+u, 8v+u+4) stored at slots (8v+2u, 8v+2u+1).
// Fragments: A = 2x float2 per (array,mb); B = 1x float2 per (array,nb).
// attn_r = qr.kr - qi.ki ; attn_i = qr.ki + qi.kr  (negation via sign XOR)
// ---------------------------------------------------------------------------
__global__ __launch_bounds__(256, 2) void qk_kernel(
    const float* __restrict__ qr, const float* __restrict__ qi,
    const float* __restrict__ kr, const float* __restrict__ ki)
{
    extern __shared__ __align__(16) u32 sm[];
    u32* Qr = sm;                 // [128][PAD]
    u32* Qi = Qr + QW;
    u32* Kr = Qi + QW;            // [64][PAD]
    u32* Ki = Kr + KW;
    __shared__ float sMin[128][2], sMax[128][2];

    const int tid = threadIdx.x, wid = tid >> 5, lane = tid & 31;
    const int kt = blockIdx.x, qt = blockIdx.y, bh = blockIdx.z;
    const int fr = tid >> 5;
    const int fv = lane >> 2, fu = lane & 3;
    const int c0 = 8 * fv + fu;          // logical col pair (c0, c0+4)
    const int slot = 8 * fv + 2 * fu;    // storage slot (u64-aligned, even)

    // ---- fill: 2x LDG.32 per array-row, 1x STS.64 into permuted slots ----
    {
        const size_t qbase = ((size_t)((bh << 10) + (qt << 7))) << 6;
        const size_t kbase = ((size_t)((bh << 10) + (kt << 6))) << 6;
        #pragma unroll
        for (int it = 0; it < 16; ++it) {
            int row = fr + (it << 3);
            const float* qr_ = qr + qbase + (row << 6);
            const float* qi_ = qi + qbase + (row << 6);
            *(u64*)(Qr + row * PAD + slot) =
                pk2(tf32c(qr_[c0] * 0.125f), tf32c(qr_[c0 + 4] * 0.125f));
            *(u64*)(Qi + row * PAD + slot) =
                pk2(tf32c(qi_[c0] * 0.125f), tf32c(qi_[c0 + 4] * 0.125f));
        }
        #pragma unroll
        for (int it = 0; it < 8; ++it) {
            int row = fr + (it << 3);
            const float* kr_ = kr + kbase + (row << 6);
            const float* ki_ = ki + kbase + (row << 6);
            *(u64*)(Kr + row * PAD + slot) = pk2(tf32c(kr_[c0]), tf32c(kr_[c0 + 4]));
            *(u64*)(Ki + row * PAD + slot) = pk2(tf32c(ki_[c0]), tf32c(ki_[c0 + 4]));
        }
    }
    __syncthreads();

    // ---- compute ----
    const int wm = wid >> 1, wn = wid & 1;
    const int g = lane >> 2, tg = lane & 3;
    float accR[2][4][4] = {}, accI[2][4][4] = {};

    // hoisted base indices (u32 units)
    const int arow = wm * 32 + g;
    const u32 aB0 = (u32)(arow * PAD + 2 * tg);            // mb=0, row g
    const u32 aB1 = (u32)((arow + 8) * PAD + 2 * tg);      // mb=0, row g+8
    const u32 aB2 = (u32)((arow + 16) * PAD + 2 * tg);     // mb=1
    const u32 aB3 = (u32)((arow + 24) * PAD + 2 * tg);
    const u32 bB0 = (u32)((wn * 32 + g) * PAD + 2 * tg);   // nb stride 8*PAD

    #pragma unroll
    for (int kb = 0; kb < 8; ++kb) {
        const u32 ko = kb * 8;
        u32 aqr[2][4], aqi[2][4];
        {
            float2 t0 = *(const float2*)(Qr + aB0 + ko);
            float2 t1 = *(const float2*)(Qr + aB1 + ko);
            float2 t2 = *(const float2*)(Qr + aB2 + ko);
            float2 t3 = *(const float2*)(Qr + aB3 + ko);
            aqr[0][0] = f2u(t0.x); aqr[0][1] = f2u(t1.x);
            aqr[0][2] = f2u(t0.y); aqr[0][3] = f2u(t1.y);
            aqr[1][0] = f2u(t2.x); aqr[1][1] = f2u(t3.x);
            aqr[1][2] = f2u(t2.y); aqr[1][3] = f2u(t3.y);
            float2 s0 = *(const float2*)(Qi + aB0 + ko);
            float2 s1 = *(const float2*)(Qi + aB1 + ko);
            float2 s2 = *(const float2*)(Qi + aB2 + ko);
            float2 s3 = *(const float2*)(Qi + aB3 + ko);
            aqi[0][0] = f2u(s0.x); aqi[0][1] = f2u(s1.x);
            aqi[0][2] = f2u(s0.y); aqi[0][3] = f2u(s1.y);
            aqi[1][0] = f2u(s2.x); aqi[1][1] = f2u(s3.x);
            aqi[1][2] = f2u(s2.y); aqi[1][3] = f2u(s3.y);
        }
        #pragma unroll
        for (int nb = 0; nb < 4; ++nb) {
            float2 tr = *(const float2*)(Kr + bB0 + nb * 8 * PAD + ko);
            float2 ti = *(const float2*)(Ki + bB0 + nb * 8 * PAD + ko);
            u32 bkr[2] = { f2u(tr.x), f2u(tr.y) };
            u32 bki[2] = { f2u(ti.x), f2u(ti.y) };
            u32 bkn[2] = { bki[0] ^ NEGF, bki[1] ^ NEGF };
            #pragma unroll
            for (int mb = 0; mb < 2; ++mb) {
                mma_tf32(accR[mb][nb], aqr[mb], bkr);
                mma_tf32(accR[mb][nb], aqi[mb], bkn);
                mma_tf32(accI[mb][nb], aqr[mb], bki);
                mma_tf32(accI[mb][nb], aqi[mb], bkr);
            }
        }
    }

    // ---- epilogue: store attn + row mag^2 min/max ----
    #pragma unroll
    for (int mb = 0; mb < 2; ++mb)
        #pragma unroll
        for (int half = 0; half < 2; ++half) {
            int rl = wm * 32 + mb * 16 + half * 8 + g;
            size_t ab = (((size_t)((bh << 10) + (qt << 7) + rl)) << 10)
                      + (kt << 6) + wn * 32 + tg * 2;
            float mn = 3.4e38f, mx = 0.0f;
            #pragma unroll
            for (int nb = 0; nb < 4; ++nb) {
                float x0 = accR[mb][nb][half * 2], x1 = accR[mb][nb][half * 2 + 1];
                float y0 = accI[mb][nb][half * 2], y1 = accI[mb][nb][half * 2 + 1];
                *(float2*)(g_ar + ab + nb * 8) = make_float2(x0, x1);
                *(float2*)(g_ai + ab + nb * 8) = make_float2(y0, y1);
                float m0 = x0 * x0 + y0 * y0, m1 = x1 * x1 + y1 * y1;
                mn = fminf(mn, fminf(m0, m1));
                mx = fmaxf(mx, fmaxf(m0, m1));
            }
            mn = fminf(mn, __shfl_xor_sync(0xffffffffu, mn, 1));
            mn = fminf(mn, __shfl_xor_sync(0xffffffffu, mn, 2));
            mx = fmaxf(mx, __shfl_xor_sync(0xffffffffu, mx, 1));
            mx = fmaxf(mx, __shfl_xor_sync(0xffffffffu, mx, 2));
            if (tg == 0) { sMin[rl][wn] = mn; sMax[rl][wn] = mx; }
        }
    __syncthreads();
    if (tid < 128) {
        float mn = fminf(sMin[tid][0], sMin[tid][1]);
        float mx = fmaxf(sMax[tid][0], sMax[tid][1]);
        int row = (qt << 7) + tid;
        g_pmin[((bh << 10) + row) * NKT + kt] = mn;
        g_pmax[((bh << 10) + row) * NKT + kt] = mx;
    }
}

// ---------------------------------------------------------------------------
// K2: reduce 16 partials/row -> mn = sqrt(min m2), inv = 1/(mx - mn).
// ---------------------------------------------------------------------------
__global__ void minmax_kernel()
{
    int r = blockIdx.x * 256 + threadIdx.x;   // 65536 rows
    float mn2 = g_pmin[r * NKT], mx2 = g_pmax[r * NKT];
    #pragma unroll
    for (int t = 1; t < NKT; t++) {
        mn2 = fminf(mn2, g_pmin[r * NKT + t]);
        mx2 = fmaxf(mx2, g_pmax[r * NKT + t]);
    }
    float mnv = sqrtf(mn2), mxv = sqrtf(mx2);
    g_mn[r] = mnv;
    g_inv[r] = 1.0f / (mxv - mnv);
}

// ---------------------------------------------------------------------------
// K3: AV. CTA tile 128q x 64d; 16 k-chunks of 64. 8 warps (4m x 2n),
// warp tile 32q x 32d. A permuted-pair layout (float2 frags); V natural
// [64k][PAD=72] scalar loads (conflict-free: banks 8tg+g distinct).
// out_r = ar.vr - ai.vi ; out_i = ar.vi + ai.vr
// ---------------------------------------------------------------------------
__global__ __launch_bounds__(256, 2) void av_kernel(
    const float* __restrict__ vr, const float* __restrict__ vi,
    float* __restrict__ out)
{
    extern __shared__ __align__(16) u32 sm[];
    u32* Ar = sm;                 // [128][PAD] permuted pairs
    u32* Ai = Ar + QW;
    u32* Vr = Ai + QW;            // [64][PAD] natural
    u32* Vi = Vr + KW;
    __shared__ float smn[128], sinv[128];

    const int tid = threadIdx.x, wid = tid >> 5, lane = tid & 31;
    const int qt = blockIdx.x, bh = blockIdx.y;
    const int fr = tid >> 5;
    const int fv = lane >> 2, fu = lane & 3;
    const int c0 = 8 * fv + fu;
    const int slot = 8 * fv + 2 * fu;
    const int cp2 = (tid & 31) * 2;

    if (tid < 128) {
        int r = (bh << 10) + (qt << 7) + tid;
        float mnv = g_mn[r], invv = g_inv[r];
        sinv[tid] = invv;
        smn[tid] = mnv * invv;   // pre-multiplied
    }
    __syncthreads();

    const int wm = wid >> 1, wn = wid & 1;
    const int g = lane >> 2, tg = lane & 3;
    float accR[2][4][4] = {}, accI[2][4][4] = {};

    const int arow = wm * 32 + g;
    const u32 aB0 = (u32)(arow * PAD + 2 * tg);
    const u32 aB1 = (u32)((arow + 8) * PAD + 2 * tg);
    const u32 aB2 = (u32)((arow + 16) * PAD + 2 * tg);
    const u32 aB3 = (u32)((arow + 24) * PAD + 2 * tg);

    const size_t abase = ((size_t)((bh << 10) + (qt << 7))) << 10;
    const size_t vbase = ((size_t)(bh << 10)) << 6;

    for (int c = 0; c < 16; ++c) {
        // A fill: normalized attn cols (c0, c0+4) -> one STS.64 per array
        #pragma unroll
        for (int it = 0; it < 16; ++it) {
            int row = fr + (it << 3);
            const float* ar_ = g_ar + abase + ((size_t)row << 10) + (c << 6);
            const float* ai_ = g_ai + abase + ((size_t)row << 10) + (c << 6);
            float ax = ar_[c0], ay = ar_[c0 + 4];
            float bx = ai_[c0], by = ai_[c0 + 4];
            float invv = sinv[row], mni = smn[row];
            float f0 = invv - mni * rsqrtf(ax * ax + bx * bx);
            float f1 = invv - mni * rsqrtf(ay * ay + by * by);
            *(u64*)(Ar + row * PAD + slot) = pk2(tf32c(ax * f0), tf32c(ay * f1));
            *(u64*)(Ai + row * PAD + slot) = pk2(tf32c(bx * f0), tf32c(by * f1));
        }
        // V fill: natural [64k][64d] -> tf32 (STS.64)
        #pragma unroll
        for (int it = 0; it < 8; ++it) {
            int krow = fr + (it << 3);
            size_t vo = vbase + ((size_t)((c << 6) + krow) << 6) + cp2;
            float2 x = *(const float2*)(vr + vo);
            float2 y = *(const float2*)(vi + vo);
            *(u64*)(Vr + krow * PAD + cp2) = pk2(tf32c(x.x), tf32c(x.y));
            *(u64*)(Vi + krow * PAD + cp2) = pk2(tf32c(y.x), tf32c(y.y));
        }
        __syncthreads();

        #pragma unroll
        for (int kb = 0; kb < 8; ++kb) {
            const u32 ko = kb * 8;
            const int kc = kb * 8 + tg;
            u32 aar[2][4], aai[2][4];
            {
                float2 t0 = *(const float2*)(Ar + aB0 + ko);
                float2 t1 = *(const float2*)(Ar + aB1 + ko);
                float2 t2 = *(const float2*)(Ar + aB2 + ko);
                float2 t3 = *(const float2*)(Ar + aB3 + ko);
                aar[0][0] = f2u(t0.x); aar[0][1] = f2u(t1.x);
                aar[0][2] = f2u(t0.y); aar[0][3] = f2u(t1.y);
                aar[1][0] = f2u(t2.x); aar[1][1] = f2u(t3.x);
                aar[1][2] = f2u(t2.y); aar[1][3] = f2u(t3.y);
                float2 s0 = *(const float2*)(Ai + aB0 + ko);
                float2 s1 = *(const float2*)(Ai + aB1 + ko);
                float2 s2 = *(const float2*)(Ai + aB2 + ko);
                float2 s3 = *(const float2*)(Ai + aB3 + ko);
                aai[0][0] = f2u(s0.x); aai[0][1] = f2u(s1.x);
                aai[0][2] = f2u(s0.y); aai[0][3] = f2u(s1.y);
                aai[1][0] = f2u(s2.x); aai[1][1] = f2u(s3.x);
                aai[1][2] = f2u(s2.y); aai[1][3] = f2u(s3.y);
            }
            #pragma unroll
            for (int nb = 0; nb < 4; ++nb) {
                int n0 = wn * 32 + nb * 8 + g;
                u32 bvr[2], bvi[2], bvn[2];
                bvr[0] = Vr[kc * PAD + n0];       bvr[1] = Vr[(kc + 4) * PAD + n0];
                bvi[0] = Vi[kc * PAD + n0];       bvi[1] = Vi[(kc + 4) * PAD + n0];
                bvn[0] = bvi[0] ^ NEGF;           bvn[1] = bvi[1] ^ NEGF;
                #pragma unroll
                for (int mb = 0; mb < 2; ++mb) {
                    mma_tf32(accR[mb][nb], aar[mb], bvr);
                    mma_tf32(accR[mb][nb], aai[mb], bvn);
                    mma_tf32(accI[mb][nb], aar[mb], bvi);
                    mma_tf32(accI[mb][nb], aai[mb], bvr);
                }
            }
        }
        __syncthreads();
    }

    // ---- epilogue: out[2][64][1024][64], imag at +4194304 ----
    #pragma unroll
    for (int mb = 0; mb < 2; ++mb)
        #pragma unroll
        for (int half = 0; half < 2; ++half) {
            int row = (qt << 7) + wm * 32 + mb * 16 + half * 8 + g;
            int d = wn * 32 + tg * 2;
            size_t ob = ((size_t)((bh << 10) + row) << 6) + d;
            #pragma unroll
            for (int nb = 0; nb < 4; ++nb) {
                *(float2*)(out + ob + nb * 8) =
                    make_float2(accR[mb][nb][half * 2], accR[mb][nb][half * 2 + 1]);
                *(float2*)(out + ob + nb * 8 + 4194304) =
                    make_float2(accI[mb][nb][half * 2], accI[mb][nb][half * 2 + 1]);
            }
        }
}

extern "C" void kernel_launch(void* const* d_in, const int* in_sizes, int n_in,
                              void* d_out, int out_size)
{
    (void)in_sizes; (void)n_in; (void)out_size;
    const float* qr = (const float*)d_in[0];
    const float* qi = (const float*)d_in[1];
    const float* kr = (const float*)d_in[2];
    const float* ki = (const float*)d_in[3];
    const float* vr = (const float*)d_in[4];
    const float* vi = (const float*)d_in[5];
    float* out = (float*)d_out;

    const int smem = (2 * QW + 2 * KW) * 4;   // 110592 B
    cudaFuncSetAttribute(qk_kernel, cudaFuncAttributeMaxDynamicSharedMemorySize, smem);
    cudaFuncSetAttribute(av_kernel, cudaFuncAttributeMaxDynamicSharedMemorySize, smem);

    qk_kernel<<<dim3(16, 8, 64), 256, smem>>>(qr, qi, kr, ki);
    minmax_kernel<<<256, 256>>>();
    av_kernel<<<dim3(8, 64), 256, smem>>>(vr, vi, out);
}

// round 17
// speedup vs baseline: 1.7590x; 1.7590x over previous
#include <cuda_runtime.h>
#include <cstdint>

// Complex attention, single-pass TF32 mma.m16n8k8. B=8 H=8 S=1024 D=64.
// R17 = R13 + interleaved (r,i) attn spill (STG.128/LDG.128) + V PAD 72.
// K1: attn=(q/8).k -> spill + per-(row,ktile) mag^2 min/max  [128q x 64k]
// K2: row min/max reduce
// K3: normalize(attn) @ v                                    [128q x 64d]
// attn_r = qr.kr - qi.ki ; attn_i = qr.ki + qi.kr  (negation via sign XOR)

#define NKT 16
typedef unsigned long long u64;
typedef uint32_t u32;

__device__ float g_a[(size_t)2 * 64 * 1024 * 1024];   // 512 MB, (r,i) interleaved
__device__ float g_pmin[64 * 1024 * NKT];
__device__ float g_pmax[64 * 1024 * NKT];
__device__ float g_mn[64 * 1024];
__device__ float g_inv[64 * 1024];

#define PAD 68            // u32 per row (A/Q/K arrays): 68%32==4 -> conflict-free
#define PADV 72           // u32 per row (V arrays): 72%32==8 -> conflict-free B-pattern
#define NEGF 0x80000000u
#define QWORDS (128 * PAD)
#define KWORDS (64 * PAD)
#define VWORDS (64 * PADV)

__device__ __forceinline__ u32 tf32c(float x) {
    u32 r; asm("cvt.rna.tf32.f32 %0, %1;" : "=r"(r) : "f"(x)); return r;
}
__device__ __forceinline__ u64 pk2(u32 lo, u32 hi) {
    return (u64)lo | ((u64)hi << 32);
}
__device__ __forceinline__ void mma_tf32(float* c, const u32* a, const u32* b) {
    asm volatile("mma.sync.aligned.m16n8k8.row.col.f32.tf32.tf32.f32 "
        "{%0,%1,%2,%3}, {%4,%5,%6,%7}, {%8,%9}, {%0,%1,%2,%3};"
        : "+f"(c[0]), "+f"(c[1]), "+f"(c[2]), "+f"(c[3])
        : "r"(a[0]), "r"(a[1]), "r"(a[2]), "r"(a[3]), "r"(b[0]), "r"(b[1]));
}

// A fragment (m16k8): a0(g,tg) a1(g+8,tg) a2(g,tg+4) a3(g+8,tg+4)
__device__ __forceinline__ void ldA(u32* a, const u32* base, int row, int col) {
    a[0] = base[row * PAD + col];
    a[1] = base[(row + 8) * PAD + col];
    a[2] = base[row * PAD + col + 4];
    a[3] = base[(row + 8) * PAD + col + 4];
}

// ---------------------------------------------------------------------------
// K1: QK. CTA tile 128q x 64k, 8 warps (4m x 2n), warp tile 32q x 32k.
// smem: Q (re,im) fp32->tf32 [128][PAD], K (re,im) [64][PAD]. 2 CTAs/SM.
// ---------------------------------------------------------------------------
__global__ __launch_bounds__(256, 2) void qk_kernel(
    const float* __restrict__ qr, const float* __restrict__ qi,
    const float* __restrict__ kr, const float* __restrict__ ki)
{
    extern __shared__ __align__(16) u32 sm[];
    u32* Qr = sm;                 // [128][PAD]
    u32* Qi = Qr + QWORDS;
    u32* Kr = Qi + QWORDS;        // [64][PAD]
    u32* Ki = Kr + KWORDS;
    __shared__ float sMin[128][2], sMax[128][2];

    const int tid = threadIdx.x, wid = tid >> 5, lane = tid & 31;
    const int kt = blockIdx.x, qt = blockIdx.y, bh = blockIdx.z;
    const int fr = tid >> 5, cp2 = (tid & 31) * 2;

    // ---- fill (coalesced LDG.64, cvt, STS.64) ----
    {
        const size_t qbase = ((size_t)((bh << 10) + (qt << 7))) << 6;
        const size_t kbase = ((size_t)((bh << 10) + (kt << 6))) << 6;
        #pragma unroll
        for (int it = 0; it < 16; ++it) {
            int row = fr + (it << 3);
            float2 a = *(const float2*)(qr + qbase + (row << 6) + cp2);
            float2 b = *(const float2*)(qi + qbase + (row << 6) + cp2);
            *(u64*)(Qr + row * PAD + cp2) = pk2(tf32c(a.x * 0.125f), tf32c(a.y * 0.125f));
            *(u64*)(Qi + row * PAD + cp2) = pk2(tf32c(b.x * 0.125f), tf32c(b.y * 0.125f));
        }
        #pragma unroll
        for (int it = 0; it < 8; ++it) {
            int row = fr + (it << 3);
            float2 c = *(const float2*)(kr + kbase + (row << 6) + cp2);
            float2 d = *(const float2*)(ki + kbase + (row << 6) + cp2);
            *(u64*)(Kr + row * PAD + cp2) = pk2(tf32c(c.x), tf32c(c.y));
            *(u64*)(Ki + row * PAD + cp2) = pk2(tf32c(d.x), tf32c(d.y));
        }
    }
    __syncthreads();

    // ---- compute (R13 verbatim) ----
    const int wm = wid >> 1, wn = wid & 1;
    const int g = lane >> 2, tg = lane & 3;
    float accR[2][4][4] = {}, accI[2][4][4] = {};

    #pragma unroll
    for (int kb = 0; kb < 8; ++kb) {
        const int kc = kb * 8 + tg;
        u32 aqr[2][4], aqi[2][4];
        #pragma unroll
        for (int mb = 0; mb < 2; ++mb) {
            int row = wm * 32 + mb * 16 + g;
            ldA(aqr[mb], Qr, row, kc);
            ldA(aqi[mb], Qi, row, kc);
        }
        #pragma unroll
        for (int nb = 0; nb < 4; ++nb) {
            int n0 = wn * 32 + nb * 8 + g;
            u32 bkr[2], bki[2], bkn[2];
            bkr[0] = Kr[n0 * PAD + kc];     bkr[1] = Kr[n0 * PAD + kc + 4];
            bki[0] = Ki[n0 * PAD + kc];     bki[1] = Ki[n0 * PAD + kc + 4];
            bkn[0] = bki[0] ^ NEGF;         bkn[1] = bki[1] ^ NEGF;
            #pragma unroll
            for (int mb = 0; mb < 2; ++mb) {
                mma_tf32(accR[mb][nb], aqr[mb], bkr);
                mma_tf32(accR[mb][nb], aqi[mb], bkn);
                mma_tf32(accI[mb][nb], aqr[mb], bki);
                mma_tf32(accI[mb][nb], aqi[mb], bkr);
            }
        }
    }

    // ---- epilogue: interleaved attn store (STG.128) + row mag^2 min/max ----
    #pragma unroll
    for (int mb = 0; mb < 2; ++mb)
        #pragma unroll
        for (int half = 0; half < 2; ++half) {
            int rl = wm * 32 + mb * 16 + half * 8 + g;
            size_t ab = ((((size_t)((bh << 10) + (qt << 7) + rl)) << 10)
                      + (kt << 6) + wn * 32 + tg * 2) << 1;   // interleaved index
            float mn = 3.4e38f, mx = 0.0f;
            #pragma unroll
            for (int nb = 0; nb < 4; ++nb) {
                float x0 = accR[mb][nb][half * 2], x1 = accR[mb][nb][half * 2 + 1];
                float y0 = accI[mb][nb][half * 2], y1 = accI[mb][nb][half * 2 + 1];
                *(float4*)(g_a + ab + nb * 16) = make_float4(x0, y0, x1, y1);
                float m0 = x0 * x0 + y0 * y0, m1 = x1 * x1 + y1 * y1;
                mn = fminf(mn, fminf(m0, m1));
                mx = fmaxf(mx, fmaxf(m0, m1));
            }
            mn = fminf(mn, __shfl_xor_sync(0xffffffffu, mn, 1));
            mn = fminf(mn, __shfl_xor_sync(0xffffffffu, mn, 2));
            mx = fmaxf(mx, __shfl_xor_sync(0xffffffffu, mx, 1));
            mx = fmaxf(mx, __shfl_xor_sync(0xffffffffu, mx, 2));
            if (tg == 0) { sMin[rl][wn] = mn; sMax[rl][wn] = mx; }
        }
    __syncthreads();
    if (tid < 128) {
        float mn = fminf(sMin[tid][0], sMin[tid][1]);
        float mx = fmaxf(sMax[tid][0], sMax[tid][1]);
        int row = (qt << 7) + tid;
        g_pmin[((bh << 10) + row) * NKT + kt] = mn;
        g_pmax[((bh << 10) + row) * NKT + kt] = mx;
    }
}

// ---------------------------------------------------------------------------
// K2: reduce 16 partials/row -> mn = sqrt(min m2), inv = 1/(mx - mn).
// ---------------------------------------------------------------------------
__global__ void minmax_kernel()
{
    int r = blockIdx.x * 256 + threadIdx.x;   // 65536 rows
    float mn2 = g_pmin[r * NKT], mx2 = g_pmax[r * NKT];
    #pragma unroll
    for (int t = 1; t < NKT; t++) {
        mn2 = fminf(mn2, g_pmin[r * NKT + t]);
        mx2 = fmaxf(mx2, g_pmax[r * NKT + t]);
    }
    float mnv = sqrtf(mn2), mxv = sqrtf(mx2);
    g_mn[r] = mnv;
    g_inv[r] = 1.0f / (mxv - mnv);
}

// ---------------------------------------------------------------------------
// K3: AV. CTA tile 128q x 64d; 16 k-chunks of 64. 8 warps (4m x 2n),
// warp tile 32q x 32d. A = normalized attn [128q][PAD] (fill via LDG.128 of
// interleaved spill); V natural [64k][PADV] (conflict-free B-pattern).
// out_r = ar.vr - ai.vi ; out_i = ar.vi + ai.vr
// ---------------------------------------------------------------------------
__global__ __launch_bounds__(256, 2) void av_kernel(
    const float* __restrict__ vr, const float* __restrict__ vi,
    float* __restrict__ out)
{
    extern __shared__ __align__(16) u32 sm[];
    u32* Ar = sm;                 // [128][PAD]
    u32* Ai = Ar + QWORDS;
    u32* Vr = Ai + QWORDS;        // [64][PADV]
    u32* Vi = Vr + VWORDS;
    __shared__ float smn[128], sinv[128];

    const int tid = threadIdx.x, wid = tid >> 5, lane = tid & 31;
    const int qt = blockIdx.x, bh = blockIdx.y;
    const int fr = tid >> 5, cp2 = (tid & 31) * 2;

    if (tid < 128) {
        int r = (bh << 10) + (qt << 7) + tid;
        float mnv = g_mn[r], invv = g_inv[r];
        sinv[tid] = invv;
        smn[tid] = mnv * invv;   // pre-multiplied
    }
    __syncthreads();

    const int wm = wid >> 1, wn = wid & 1;
    const int g = lane >> 2, tg = lane & 3;
    float accR[2][4][4] = {}, accI[2][4][4] = {};

    const size_t abase = ((size_t)((bh << 10) + (qt << 7))) << 10;   // k-units
    const size_t vbase = ((size_t)(bh << 10)) << 6;

    for (int c = 0; c < 16; ++c) {
        // A fill: one LDG.128 per (row,it) of interleaved attn -> normalize -> tf32
        #pragma unroll
        for (int it = 0; it < 16; ++it) {
            int row = fr + (it << 3);
            size_t ao = (abase + ((size_t)row << 10) + (c << 6) + cp2) << 1;
            float4 t = *(const float4*)(g_a + ao);   // (ar0, ai0, ar1, ai1)
            float invv = sinv[row], mni = smn[row];
            float f0 = invv - mni * rsqrtf(t.x * t.x + t.y * t.y);
            float f1 = invv - mni * rsqrtf(t.z * t.z + t.w * t.w);
            *(u64*)(Ar + row * PAD + cp2) = pk2(tf32c(t.x * f0), tf32c(t.z * f1));
            *(u64*)(Ai + row * PAD + cp2) = pk2(tf32c(t.y * f0), tf32c(t.w * f1));
        }
        // V fill: natural [64k][64d] -> tf32
        #pragma unroll
        for (int it = 0; it < 8; ++it) {
            int krow = fr + (it << 3);
            size_t vo = vbase + ((size_t)((c << 6) + krow) << 6) + cp2;
            float2 x = *(const float2*)(vr + vo);
            float2 y = *(const float2*)(vi + vo);
            *(u64*)(Vr + krow * PADV + cp2) = pk2(tf32c(x.x), tf32c(x.y));
            *(u64*)(Vi + krow * PADV + cp2) = pk2(tf32c(y.x), tf32c(y.y));
        }
        __syncthreads();

        #pragma unroll
        for (int kb = 0; kb < 8; ++kb) {
            const int kc = kb * 8 + tg;
            u32 aar[2][4], aai[2][4];
            #pragma unroll
            for (int mb = 0; mb < 2; ++mb) {
                int row = wm * 32 + mb * 16 + g;
                ldA(aar[mb], Ar, row, kc);
                ldA(aai[mb], Ai, row, kc);
            }
            #pragma unroll
            for (int nb = 0; nb < 4; ++nb) {
                int n0 = wn * 32 + nb * 8 + g;
                u32 bvr[2], bvi[2], bvn[2];
                bvr[0] = Vr[kc * PADV + n0];      bvr[1] = Vr[(kc + 4) * PADV + n0];
                bvi[0] = Vi[kc * PADV + n0];      bvi[1] = Vi[(kc + 4) * PADV + n0];
                bvn[0] = bvi[0] ^ NEGF;           bvn[1] = bvi[1] ^ NEGF;
                #pragma unroll
                for (int mb = 0; mb < 2; ++mb) {
                    mma_tf32(accR[mb][nb], aar[mb], bvr);
                    mma_tf32(accR[mb][nb], aai[mb], bvn);
                    mma_tf32(accI[mb][nb], aar[mb], bvi);
                    mma_tf32(accI[mb][nb], aai[mb], bvr);
                }
            }
        }
        __syncthreads();
    }

    // ---- epilogue: out[2][64][1024][64], imag at +4194304 ----
    #pragma unroll
    for (int mb = 0; mb < 2; ++mb)
        #pragma unroll
        for (int half = 0; half < 2; ++half) {
            int row = (qt << 7) + wm * 32 + mb * 16 + half * 8 + g;
            int d = wn * 32 + tg * 2;
            size_t ob = ((size_t)((bh << 10) + row) << 6) + d;
            #pragma unroll
            for (int nb = 0; nb < 4; ++nb) {
                *(float2*)(out + ob + nb * 8) =
                    make_float2(accR[mb][nb][half * 2], accR[mb][nb][half * 2 + 1]);
                *(float2*)(out + ob + nb * 8 + 4194304) =
                    make_float2(accI[mb][nb][half * 2], accI[mb][nb][half * 2 + 1]);
            }
        }
}

extern "C" void kernel_launch(void* const* d_in, const int* in_sizes, int n_in,
                              void* d_out, int out_size)
{
    (void)in_sizes; (void)n_in; (void)out_size;
    const float* qr = (const float*)d_in[0];
    const float* qi = (const float*)d_in[1];
    const float* kr = (const float*)d_in[2];
    const float* ki = (const float*)d_in[3];
    const float* vr = (const float*)d_in[4];
    const float* vi = (const float*)d_in[5];
    float* out = (float*)d_out;

    const int smem_qk = (2 * QWORDS + 2 * KWORDS) * 4;   // 104448 B
    const int smem_av = (2 * QWORDS + 2 * VWORDS) * 4;   // 106496 B
    cudaFuncSetAttribute(qk_kernel, cudaFuncAttributeMaxDynamicSharedMemorySize, smem_qk);
    cudaFuncSetAttribute(av_kernel, cudaFuncAttributeMaxDynamicSharedMemorySize, smem_av);

    qk_kernel<<<dim3(16, 8, 64), 256, smem_qk>>>(qr, qi, kr, ki);
    minmax_kernel<<<256, 256>>>();
    av_kernel<<<dim3(8, 64), 256, smem_av>>>(vr, vi, out);
}